// round 1
// baseline (speedup 1.0000x reference)
#include <cuda_runtime.h>
#include <math.h>

// ---------------- problem constants ----------------
#define BB 4
#define NN 16384
#define HDIM 1024
#define HH 8
#define MM 32
#define DD 128
#define ZZ (BB*HH)            // 32 (b,h) batches
#define BN_TOK (BB*NN)        // 65536 tokens

// ---------------- output regions (floats) ----------------
// tuple: (out, slice_weights, temperature, bias, attn_weights)
#define R1_OUT   ((size_t)0)                                   // 4*16384*1024 = 67108864
#define R2_SW    ((size_t)67108864)                            // 32*32*16384  = 16777216
#define R3_TEMP  ((size_t)83886080)                            // 1
#define R4_BIAS  ((size_t)83886081)                            // 256
#define R5_ATTN  ((size_t)83886337)                            // 32768

// ---------------- scratch (device globals; no allocations allowed) ----------------
__device__ float g_kv[(size_t)BN_TOK * 2 * HDIM];      // [b*n][2048]  512 MB
__device__ float g_scores[(size_t)ZZ * NN * MM];       // [z][n][m]     64 MB
__device__ float g_acc[ZZ * MM * DD];                  // slice_token accumulator
__device__ float g_norm[ZZ * MM];                      // slice_norm accumulator
__device__ float g_qkv[ZZ * MM * 3 * DD];              // qkv_token
__device__ float g_ot[ZZ * MM * DD];                   // out_token
__device__ float g_out_pre[(size_t)BN_TOK * HDIM];     // pre-projection output, 256 MB

// =====================================================================
// Generic register-tiled SGEMM, NT layout: C[M,N] = A[M,K] @ B[N,K]^T (+bias[N])
// Batched via blockIdx.z with offsets (z/zdiv)*S1 + (z%zdiv)*S2.
// Requires M%BM==0, N%BN==0, K%BK==0 (true for all our calls).
// =====================================================================
template<int BM,int BN,int BK,int TM,int TN>
__global__ void __launch_bounds__((BM/TM)*(BN/TN))
sgemm_nt(const float* __restrict__ A, const float* __restrict__ B,
         float* __restrict__ C, const float* __restrict__ bias,
         int K, int lda, int ldb, int ldc,
         int zdiv, long aS1, long aS2, long bS1, long bS2, long cS1, long cS2)
{
    constexpr int NT = (BM/TM)*(BN/TN);
    constexpr int AV = (BM*BK/4)/NT;
    constexpr int BV = (BN*BK/4)/NT;
    static_assert(AV >= 1 && BV >= 1, "tile loader config");
    static_assert((BM*BK/4) % NT == 0 && (BN*BK/4) % NT == 0, "tile loader div");

    const int z = blockIdx.z;
    A += (size_t)(z / zdiv) * aS1 + (size_t)(z % zdiv) * aS2;
    B += (size_t)(z / zdiv) * bS1 + (size_t)(z % zdiv) * bS2;
    C += (size_t)(z / zdiv) * cS1 + (size_t)(z % zdiv) * cS2;

    __shared__ float As[BK][BM];
    __shared__ float Bs[BK][BN];

    const int tid = threadIdx.x;
    const int rowBase = blockIdx.y * BM;
    const int colBase = blockIdx.x * BN;
    const int tCol = tid % (BN/TN);
    const int tRow = tid / (BN/TN);

    float acc[TM][TN];
    #pragma unroll
    for (int i = 0; i < TM; i++)
        #pragma unroll
        for (int j = 0; j < TN; j++) acc[i][j] = 0.f;

    for (int k0 = 0; k0 < K; k0 += BK) {
        #pragma unroll
        for (int v = 0; v < AV; v++) {
            int idx = tid + v*NT;
            int r  = idx / (BK/4);
            int kc = (idx % (BK/4)) * 4;
            float4 t = *(const float4*)(A + (size_t)(rowBase + r)*lda + k0 + kc);
            As[kc+0][r] = t.x; As[kc+1][r] = t.y; As[kc+2][r] = t.z; As[kc+3][r] = t.w;
        }
        #pragma unroll
        for (int v = 0; v < BV; v++) {
            int idx = tid + v*NT;
            int r  = idx / (BK/4);
            int kc = (idx % (BK/4)) * 4;
            float4 t = *(const float4*)(B + (size_t)(colBase + r)*ldb + k0 + kc);
            Bs[kc+0][r] = t.x; Bs[kc+1][r] = t.y; Bs[kc+2][r] = t.z; Bs[kc+3][r] = t.w;
        }
        __syncthreads();

        #pragma unroll
        for (int kk = 0; kk < BK; kk++) {
            float a[TM], b[TN];
            #pragma unroll
            for (int i = 0; i < TM; i++) a[i] = As[kk][tRow*TM + i];
            #pragma unroll
            for (int j = 0; j < TN; j++) b[j] = Bs[kk][tCol*TN + j];
            #pragma unroll
            for (int i = 0; i < TM; i++)
                #pragma unroll
                for (int j = 0; j < TN; j++)
                    acc[i][j] += a[i] * b[j];
        }
        __syncthreads();
    }

    #pragma unroll
    for (int i = 0; i < TM; i++) {
        size_t r = (size_t)(rowBase + tRow*TM + i);
        #pragma unroll
        for (int j = 0; j < TN; j += 4) {
            int c = colBase + tCol*TN + j;
            float4 o;
            o.x = acc[i][j+0] + (bias ? bias[c+0] : 0.f);
            o.y = acc[i][j+1] + (bias ? bias[c+1] : 0.f);
            o.z = acc[i][j+2] + (bias ? bias[c+2] : 0.f);
            o.w = acc[i][j+3] + (bias ? bias[c+3] : 0.f);
            *(float4*)(C + r*ldc + c) = o;
        }
    }
}

// =====================================================================
// Zero the slice_token / slice_norm accumulators (every call; deterministic)
// =====================================================================
__global__ void zero_kernel()
{
    int i = blockIdx.x * 256 + threadIdx.x;
    if (i < ZZ*MM*DD) g_acc[i] = 0.f;
    if (i < ZZ*MM)    g_norm[i] = 0.f;
}

// =====================================================================
// Softmax over slice axis m (32 vals per token), with [n][m] -> [m][n] transpose.
// grid (NN/256, ZZ), 256 threads. Writes slice_weights directly into d_out.
// =====================================================================
__global__ void softmax_slice(const float* __restrict__ scores, float* __restrict__ w)
{
    __shared__ float ss[256*33];
    const int z = blockIdx.y;
    const int n0 = blockIdx.x * 256;
    const int tid = threadIdx.x;

    const float* sb = scores + ((size_t)z*NN + n0) * MM;
    for (int i = tid; i < 256*MM; i += 256) {
        int n = i / MM, m = i % MM;
        ss[n*33 + m] = sb[i];           // coalesced read
    }
    __syncthreads();

    float e[MM];
    float mx = -1e30f;
    #pragma unroll
    for (int m = 0; m < MM; m++) mx = fmaxf(mx, ss[tid*33 + m]);
    float sum = 0.f;
    #pragma unroll
    for (int m = 0; m < MM; m++) { e[m] = __expf(ss[tid*33 + m] - mx); sum += e[m]; }
    float inv = 1.f / sum;

    float* wb = w + (size_t)z*MM*NN + n0 + tid;
    #pragma unroll
    for (int m = 0; m < MM; m++) wb[(size_t)m*NN] = e[m] * inv;   // coalesced write
}

// =====================================================================
// slice_token split-K: per (z, 64-token chunk) block computes partial
// [32m][128d] = W_chunk @ XV_chunk and partial slice_norm; atomicAdd into acc.
// grid (NN/64, ZZ), 256 threads. smem 40 KB.
// =====================================================================
__global__ void slice_token_kernel(const float* __restrict__ w)
{
    __shared__ float  ws[MM][64];
    __shared__ float4 xvs[64][32];
    const int z = blockIdx.y, c = blockIdx.x;
    const int b = z >> 3, h = z & 7;
    const int tid = threadIdx.x;

    const float* wb = w + (size_t)z*MM*NN + (size_t)c*64;
    for (int i = tid; i < MM*64; i += 256) {
        int m = i >> 6, n = i & 63;
        ws[m][n] = wb[(size_t)m*NN + n];
    }
    const float* vb = g_kv + ((size_t)(b*NN + c*64)) * (2*HDIM) + HDIM + h*DD;
    for (int i = tid; i < 64*32; i += 256) {
        int n = i >> 5, d4 = i & 31;
        xvs[n][d4] = *(const float4*)(vb + (size_t)n*(2*HDIM) + d4*4);
    }
    __syncthreads();

    if (tid < MM) {
        float s = 0.f;
        #pragma unroll 8
        for (int n = 0; n < 64; n++) s += ws[tid][n];
        atomicAdd(&g_norm[z*MM + tid], s);
    }

    const int d4 = tid & 31, mr = tid >> 5;   // mr: 0..7 -> m = mr*4+i
    float4 a[4];
    #pragma unroll
    for (int i = 0; i < 4; i++) a[i] = make_float4(0.f,0.f,0.f,0.f);

    #pragma unroll 4
    for (int n = 0; n < 64; n++) {
        float4 xv = xvs[n][d4];
        #pragma unroll
        for (int i = 0; i < 4; i++) {
            float wv = ws[mr*4 + i][n];
            a[i].x += wv*xv.x; a[i].y += wv*xv.y; a[i].z += wv*xv.z; a[i].w += wv*xv.w;
        }
    }
    float* ab = g_acc + (size_t)z*MM*DD + (mr*4)*DD + d4*4;
    #pragma unroll
    for (int i = 0; i < 4; i++) {
        atomicAdd(ab + i*DD + 0, a[i].x);
        atomicAdd(ab + i*DD + 1, a[i].y);
        atomicAdd(ab + i*DD + 2, a[i].z);
        atomicAdd(ab + i*DD + 3, a[i].w);
    }
}

// =====================================================================
// Normalize slice_token and project to qkv_token. grid ZZ, 256 threads.
// =====================================================================
__global__ void qkv_kernel(const float* __restrict__ proj)
{
    __shared__ float st[MM*DD];
    __shared__ float inv[MM];
    const int z = blockIdx.x, h = z & 7, tid = threadIdx.x;

    if (tid < MM) inv[tid] = 1.f / (g_norm[z*MM + tid] + 1e-5f);
    __syncthreads();
    for (int i = tid; i < MM*DD; i += 256) st[i] = g_acc[(size_t)z*MM*DD + i] * inv[i >> 7];
    __syncthreads();

    const float* P = proj + (size_t)h * DD * (3*DD);
    for (int i = tid; i < MM*3*DD; i += 256) {
        int m = i / (3*DD), e = i % (3*DD);
        float s = 0.f;
        #pragma unroll 8
        for (int d = 0; d < DD; d++) s += st[m*DD + d] * P[(size_t)d*(3*DD) + e];
        g_qkv[(size_t)z*MM*3*DD + i] = s;
    }
}

// =====================================================================
// Tiny 32x32 attention per (b,h); writes attn_weights + temperature + bias.
// grid ZZ, 256 threads.
// =====================================================================
__global__ void attn_kernel(const float* __restrict__ wtq_bias, float* __restrict__ out)
{
    __shared__ float s_d[MM*MM];
    __shared__ float aw[MM*MM];
    const int z = blockIdx.x, tid = threadIdx.x;
    const float* Q  = g_qkv + (size_t)z*MM*3*DD;
    const float* Kt = Q + DD;
    const float* V  = Q + 2*DD;
    const float scale = 0.08838834764831845f;   // 128^-0.5

    for (int i = tid; i < MM*MM; i += 256) {
        int q = i >> 5, k = i & 31;
        float s = 0.f;
        #pragma unroll 8
        for (int d = 0; d < DD; d++) s += Q[q*(3*DD) + d] * Kt[k*(3*DD) + d];
        s_d[i] = s * scale;
    }
    __syncthreads();

    if (tid < MM) {
        float mx = -1e30f;
        #pragma unroll
        for (int k = 0; k < MM; k++) mx = fmaxf(mx, s_d[tid*MM + k]);
        float sum = 0.f;
        #pragma unroll
        for (int k = 0; k < MM; k++) { float e = __expf(s_d[tid*MM + k] - mx); aw[tid*MM + k] = e; sum += e; }
        float iv = 1.f / sum;
        #pragma unroll
        for (int k = 0; k < MM; k++) {
            float v = aw[tid*MM + k] * iv;
            aw[tid*MM + k] = v;
            out[R5_ATTN + (size_t)z*MM*MM + tid*MM + k] = v;
        }
    }
    __syncthreads();

    for (int i = tid; i < MM*DD; i += 256) {
        int m = i >> 7, d = i & 127;
        float s = 0.f;
        #pragma unroll
        for (int k = 0; k < MM; k++) s += aw[m*MM + k] * V[k*(3*DD) + d];
        g_ot[(size_t)z*MM*DD + i] = s;
    }

    if (z == 0) {
        if (tid == 0) out[R3_TEMP] = 1.0f;
        if (tid < HH*MM) out[R4_BIAS + tid] = wtq_bias[tid];
    }
}

// =====================================================================
// Scatter: out_pre[b][n][h*128+d] = sum_m out_token[z][m][d] * w[z][m][n]
// grid (NN/32, ZZ), 256 threads.
// =====================================================================
__global__ void scatter_kernel(const float* __restrict__ w)
{
    __shared__ float4 ot4[MM][32];
    __shared__ float  wsm[MM][33];
    const int z = blockIdx.y, t = blockIdx.x;
    const int b = z >> 3, h = z & 7, tid = threadIdx.x;

    for (int i = tid; i < MM*32; i += 256)
        ot4[i >> 5][i & 31] = ((const float4*)g_ot)[(size_t)z*MM*32 + i];

    const int n0 = t * 32;
    const float* wb = w + (size_t)z*MM*NN + n0;
    for (int i = tid; i < MM*32; i += 256) {
        int m = i >> 5, n = i & 31;
        wsm[m][n] = wb[(size_t)m*NN + n];
    }
    __syncthreads();

    const int d4 = tid & 31, nl = tid >> 5;   // nl: 0..7
    #pragma unroll
    for (int p = 0; p < 4; p++) {
        int n = p*8 + nl;
        float4 a = make_float4(0.f,0.f,0.f,0.f);
        #pragma unroll
        for (int m = 0; m < MM; m++) {
            float wv = wsm[m][n];
            float4 o = ot4[m][d4];
            a.x += wv*o.x; a.y += wv*o.y; a.z += wv*o.z; a.w += wv*o.w;
        }
        *(float4*)&g_out_pre[((size_t)(b*NN + n0 + n))*HDIM + h*DD + d4*4] = a;
    }
}

// =====================================================================
// kernel_launch
// inputs: x, wt_kv_weight, wt_kv_bias, wtq, wtq_bias, qkv_proj, out_weight, out_bias
// =====================================================================
extern "C" void kernel_launch(void* const* d_in, const int* in_sizes, int n_in,
                              void* d_out, int out_size)
{
    const float* x         = (const float*)d_in[0];
    const float* wkv       = (const float*)d_in[1];
    const float* bkv       = (const float*)d_in[2];
    const float* wtq       = (const float*)d_in[3];
    const float* wtq_bias  = (const float*)d_in[4];
    const float* qkv_proj  = (const float*)d_in[5];
    const float* out_w     = (const float*)d_in[6];
    const float* out_b     = (const float*)d_in[7];
    float* out = (float*)d_out;

    float *kv, *scores, *out_pre;
    cudaGetSymbolAddress((void**)&kv, g_kv);
    cudaGetSymbolAddress((void**)&scores, g_scores);
    cudaGetSymbolAddress((void**)&out_pre, g_out_pre);

    float* sw = out + R2_SW;

    // 0) zero split-K accumulators
    zero_kernel<<<(ZZ*MM*DD + 255)/256, 256>>>();

    // 1) kv = x @ Wkv^T + b : [65536,1024] x [2048,1024]^T -> [65536,2048]
    sgemm_nt<128,128,8,8,8><<<dim3(2048/128, BN_TOK/128, 1), 256>>>(
        x, wkv, kv, bkv, HDIM, HDIM, HDIM, 2*HDIM,
        1, 0, 0, 0, 0, 0, 0);

    // 2) slice_scores[z][n][m] = xk[z] @ wtq[h]^T : batched [16384,128] x [32,128]^T
    sgemm_nt<128,32,16,8,4><<<dim3(1, NN/128, ZZ), 128>>>(
        kv, wtq, scores, nullptr, DD, 2*HDIM, DD, MM,
        /*zdiv=*/HH,
        /*aS1=*/(long)NN*2*HDIM, /*aS2=*/(long)DD,
        /*bS1=*/0,               /*bS2=*/(long)MM*DD,
        /*cS1=*/(long)HH*NN*MM,  /*cS2=*/(long)NN*MM);

    // 3) softmax over m, transpose -> slice_weights (directly in d_out)
    softmax_slice<<<dim3(NN/256, ZZ), 256>>>(scores, sw);

    // 4) slice_token = slice_weights @ xv (split-K + atomics), slice_norm
    slice_token_kernel<<<dim3(NN/64, ZZ), 256>>>(sw);

    // 5) normalize + qkv projection
    qkv_kernel<<<ZZ, 256>>>(qkv_proj);

    // 6) tiny attention; also temperature / bias / attn_weights outputs
    attn_kernel<<<ZZ, 256>>>(wtq_bias, out);

    // 7) scatter out_token back to tokens
    scatter_kernel<<<dim3(NN/32, ZZ), 256>>>(sw);

    // 8) out = out_pre @ Wout^T + b -> d_out region 1
    sgemm_nt<128,128,8,8,8><<<dim3(HDIM/128, BN_TOK/128, 1), 256>>>(
        out_pre, out_w, out, out_b, HDIM, HDIM, HDIM, HDIM,
        1, 0, 0, 0, 0, 0, 0);
}

// round 14
// speedup vs baseline: 3.1917x; 3.1917x over previous
#include <cuda_runtime.h>
#include <math.h>
#include <stdint.h>

// ---------------- problem constants ----------------
#define BB 4
#define NN 16384
#define HDIM 1024
#define HH 8
#define MM 32
#define DD 128
#define ZZ (BB*HH)            // 32 (b,h) batches
#define BN_TOK (BB*NN)        // 65536 tokens

// ---------------- output regions (floats) ----------------
#define R1_OUT   ((size_t)0)
#define R2_SW    ((size_t)67108864)
#define R3_TEMP  ((size_t)83886080)
#define R4_BIAS  ((size_t)83886081)
#define R5_ATTN  ((size_t)83886337)

// ---------------- scratch ----------------
__device__ float g_kv[(size_t)BN_TOK * 2 * HDIM];      // 512 MB
__device__ float g_scores[(size_t)ZZ * NN * MM];       // 64 MB
__device__ float g_acc[ZZ * MM * DD];
__device__ float g_norm[ZZ * MM];
__device__ float g_qkv[ZZ * MM * 3 * DD];
__device__ float g_ot[ZZ * MM * DD];
__device__ float g_out_pre[(size_t)BN_TOK * HDIM];     // 256 MB
__device__ float g_xr[(size_t)BN_TOK * HDIM];          // tf32-rounded x
__device__ float g_wkvr[2 * HDIM * HDIM];              // tf32-rounded wt_kv
__device__ float g_owr[HDIM * HDIM];                   // tf32-rounded out_w

// =====================================================================
// helpers
// =====================================================================
__device__ __forceinline__ uint32_t cvta_s(const void* p) {
    uint32_t a;
    asm("{ .reg .u64 t; cvta.to.shared.u64 t, %1; cvt.u32.u64 %0, t; }" : "=r"(a) : "l"(p));
    return a;
}
__device__ __forceinline__ uint32_t sw128(uint32_t o) { return o ^ ((o >> 3) & 0x70); }
__device__ __forceinline__ void cpasync16(uint32_t s, const void* g) {
    asm volatile("cp.async.cg.shared.global [%0], [%1], 16;" :: "r"(s), "l"(g));
}
__device__ __forceinline__ float rtf32(float x) {
    uint32_t u; asm("cvt.rna.tf32.f32 %0, %1;" : "=r"(u) : "f"(x));
    return __uint_as_float(u);
}
__device__ __forceinline__ void ldmx4(uint32_t* r, uint32_t addr) {
    asm volatile("ldmatrix.sync.aligned.m8n8.x4.shared.b16 {%0,%1,%2,%3}, [%4];"
        : "=r"(r[0]), "=r"(r[1]), "=r"(r[2]), "=r"(r[3]) : "r"(addr));
}
__device__ __forceinline__ void mma_tf32(float* d, const uint32_t* a, const uint32_t* b) {
    asm volatile(
        "mma.sync.aligned.m16n8k8.row.col.f32.tf32.tf32.f32 "
        "{%0,%1,%2,%3}, {%4,%5,%6,%7}, {%8,%9}, {%0,%1,%2,%3};"
        : "+f"(d[0]), "+f"(d[1]), "+f"(d[2]), "+f"(d[3])
        : "r"(a[0]), "r"(a[1]), "r"(a[2]), "r"(a[3]), "r"(b[0]), "r"(b[1]));
}

// =====================================================================
// tf32 tensor-core GEMM via mma.sync:  C[M,N] = A[M,K] @ B[N,K]^T + bias[N]
// BM=128, BN=128, 32-float K chunks, 4-stage cp.async ring, SW128 swizzle.
// A,B pre-rounded to tf32 (rna). M%128==0, N%128==0, K%32==0.
// =====================================================================
#define TC_BM 128
#define TC_BN 128
#define TC_ST 4
#define TC_ABYTES (TC_BM*128)            // 16 KB / stage
#define TC_BBYTES (TC_BN*128)            // 16 KB / stage
#define TC_STAGE  (TC_ABYTES + TC_BBYTES)
#define TC_DSMEM  (1024 + TC_ST*TC_STAGE)

__global__ void __launch_bounds__(256, 1)
tc_gemm(const float* __restrict__ A, const float* __restrict__ B,
        const float* __restrict__ bias, float* __restrict__ C,
        int lda, int ldb, int ldc, int K)
{
    extern __shared__ char smem_raw[];
    const uint32_t sb0 = cvta_s(smem_raw);
    const uint32_t sb  = (sb0 + 1023) & ~1023u;       // 1024-aligned tile base

    const int tid = threadIdx.x;
    const int wid = tid >> 5, lane = tid & 31;
    const int warpM = wid & 1;                        // 2 warps over M (64 rows each)
    const int warpN = wid >> 1;                       // 4 warps over N (32 cols each)
    const int rowBase = blockIdx.y * TC_BM;
    const int colBase = blockIdx.x * TC_BN;

    const float* Ag = A + (size_t)rowBase * lda;
    const float* Bg = B + (size_t)colBase * ldb;
    const int KC = K >> 5;

    float acc[4][4][4];
    #pragma unroll
    for (int mt = 0; mt < 4; mt++)
        #pragma unroll
        for (int nt = 0; nt < 4; nt++)
            #pragma unroll
            for (int i = 0; i < 4; i++) acc[mt][nt][i] = 0.f;

    auto load_stage = [&](int s, int c) {
        const uint32_t sa = sb + s * TC_STAGE;
        const uint32_t sB = sa + TC_ABYTES;
        const float* ga = Ag + c * 32;
        const float* gb = Bg + c * 32;
        #pragma unroll
        for (int i = 0; i < 4; i++) {                 // A: 128 rows x 8 x 16B
            int idx = tid + i * 256;
            int r = idx >> 3, cc = idx & 7;
            cpasync16(sa + sw128(r * 128 + cc * 16), ga + (size_t)r * lda + cc * 4);
        }
        #pragma unroll
        for (int i = 0; i < 4; i++) {                 // B: 128 rows x 8 x 16B
            int idx = tid + i * 256;
            int r = idx >> 3, cc = idx & 7;
            cpasync16(sB + sw128(r * 128 + cc * 16), gb + (size_t)r * ldb + cc * 4);
        }
        asm volatile("cp.async.commit_group;" ::: "memory");
    };

    // prefetch first ST-1 stages
    #pragma unroll
    for (int s = 0; s < TC_ST - 1; s++) load_stage(s, s);

    // fragment address components (constant across chunks)
    const uint32_t aRow = warpM * 64 + (lane & 15);           // + mt*16
    const uint32_t aColB = (lane >> 4) * 16;                  // 16B col half
    const uint32_t bRow = warpN * 32 + ((lane >> 4) << 3) + (lane & 7);   // + nt2*16
    const uint32_t bColB = ((lane >> 3) & 1) * 16;

    for (int c = 0; c < KC; c++) {
        const int s = c & (TC_ST - 1);
        asm volatile("cp.async.wait_group %0;" :: "n"(TC_ST - 2) : "memory");
        __syncthreads();

        const uint32_t sa = sb + s * TC_STAGE;
        const uint32_t sB = sa + TC_ABYTES;
        #pragma unroll
        for (int ks = 0; ks < 4; ks++) {
            uint32_t af[4][4], bf[2][4];
            #pragma unroll
            for (int mt = 0; mt < 4; mt++)
                ldmx4(af[mt], sa + sw128((aRow + mt * 16) * 128 + ks * 32 + aColB));
            #pragma unroll
            for (int nt2 = 0; nt2 < 2; nt2++)
                ldmx4(bf[nt2], sB + sw128((bRow + nt2 * 16) * 128 + ks * 32 + bColB));
            #pragma unroll
            for (int mt = 0; mt < 4; mt++)
                #pragma unroll
                for (int nt = 0; nt < 4; nt++)
                    mma_tf32(acc[mt][nt], af[mt], &bf[nt >> 1][(nt & 1) * 2]);
        }

        const int cn = c + TC_ST - 1;
        if (cn < KC) load_stage((cn & (TC_ST - 1)), cn);
        else asm volatile("cp.async.commit_group;" ::: "memory");   // keep group count in sync
    }

    // ---------------- epilogue: direct float2 stores ----------
    const int erow = lane >> 2;            // 0..7
    const int ecol = (lane & 3) * 2;       // 0,2,4,6
    #pragma unroll
    for (int mt = 0; mt < 4; mt++) {
        #pragma unroll
        for (int nt = 0; nt < 4; nt++) {
            int col = colBase + warpN * 32 + nt * 8 + ecol;
            float2 bz = *(const float2*)(bias + col);
            size_t r0 = (size_t)(rowBase + warpM * 64 + mt * 16 + erow);
            float2 o0 = { acc[mt][nt][0] + bz.x, acc[mt][nt][1] + bz.y };
            float2 o1 = { acc[mt][nt][2] + bz.x, acc[mt][nt][3] + bz.y };
            *(float2*)(C + r0 * ldc + col)       = o0;
            *(float2*)(C + (r0 + 8) * ldc + col) = o1;
        }
    }
}

// =====================================================================
// round-to-nearest tf32 pre-pass
// =====================================================================
__global__ void round_tf32_kernel(const float* __restrict__ in, float* __restrict__ out, int n4)
{
    int i = blockIdx.x * 256 + threadIdx.x;
    if (i < n4) {
        float4 v = ((const float4*)in)[i];
        float4 o;
        o.x = rtf32(v.x); o.y = rtf32(v.y); o.z = rtf32(v.z); o.w = rtf32(v.w);
        ((float4*)out)[i] = o;
    }
}

// =====================================================================
// Generic register-tiled SGEMM (used only for slice_scores)
// =====================================================================
template<int BM,int BN,int BK,int TM,int TN>
__global__ void __launch_bounds__((BM/TM)*(BN/TN))
sgemm_nt(const float* __restrict__ A, const float* __restrict__ B,
         float* __restrict__ C, const float* __restrict__ bias,
         int K, int lda, int ldb, int ldc,
         int zdiv, long aS1, long aS2, long bS1, long bS2, long cS1, long cS2)
{
    constexpr int NT = (BM/TM)*(BN/TN);
    constexpr int AV = (BM*BK/4)/NT;
    constexpr int BV = (BN*BK/4)/NT;

    const int z = blockIdx.z;
    A += (size_t)(z / zdiv) * aS1 + (size_t)(z % zdiv) * aS2;
    B += (size_t)(z / zdiv) * bS1 + (size_t)(z % zdiv) * bS2;
    C += (size_t)(z / zdiv) * cS1 + (size_t)(z % zdiv) * cS2;

    __shared__ float As[BK][BM];
    __shared__ float Bs[BK][BN];

    const int tid = threadIdx.x;
    const int rowBase = blockIdx.y * BM;
    const int colBase = blockIdx.x * BN;
    const int tCol = tid % (BN/TN);
    const int tRow = tid / (BN/TN);

    float acc[TM][TN];
    #pragma unroll
    for (int i = 0; i < TM; i++)
        #pragma unroll
        for (int j = 0; j < TN; j++) acc[i][j] = 0.f;

    for (int k0 = 0; k0 < K; k0 += BK) {
        #pragma unroll
        for (int v = 0; v < AV; v++) {
            int idx = tid + v*NT;
            int r  = idx / (BK/4);
            int kc = (idx % (BK/4)) * 4;
            float4 t = *(const float4*)(A + (size_t)(rowBase + r)*lda + k0 + kc);
            As[kc+0][r] = t.x; As[kc+1][r] = t.y; As[kc+2][r] = t.z; As[kc+3][r] = t.w;
        }
        #pragma unroll
        for (int v = 0; v < BV; v++) {
            int idx = tid + v*NT;
            int r  = idx / (BK/4);
            int kc = (idx % (BK/4)) * 4;
            float4 t = *(const float4*)(B + (size_t)(colBase + r)*ldb + k0 + kc);
            Bs[kc+0][r] = t.x; Bs[kc+1][r] = t.y; Bs[kc+2][r] = t.z; Bs[kc+3][r] = t.w;
        }
        __syncthreads();

        #pragma unroll
        for (int kk = 0; kk < BK; kk++) {
            float a[TM], b[TN];
            #pragma unroll
            for (int i = 0; i < TM; i++) a[i] = As[kk][tRow*TM + i];
            #pragma unroll
            for (int j = 0; j < TN; j++) b[j] = Bs[kk][tCol*TN + j];
            #pragma unroll
            for (int i = 0; i < TM; i++)
                #pragma unroll
                for (int j = 0; j < TN; j++)
                    acc[i][j] += a[i] * b[j];
        }
        __syncthreads();
    }

    #pragma unroll
    for (int i = 0; i < TM; i++) {
        size_t r = (size_t)(rowBase + tRow*TM + i);
        #pragma unroll
        for (int j = 0; j < TN; j += 4) {
            int c = colBase + tCol*TN + j;
            float4 o;
            o.x = acc[i][j+0] + (bias ? bias[c+0] : 0.f);
            o.y = acc[i][j+1] + (bias ? bias[c+1] : 0.f);
            o.z = acc[i][j+2] + (bias ? bias[c+2] : 0.f);
            o.w = acc[i][j+3] + (bias ? bias[c+3] : 0.f);
            *(float4*)(C + r*ldc + c) = o;
        }
    }
}

// =====================================================================
__global__ void zero_kernel()
{
    int i = blockIdx.x * 256 + threadIdx.x;
    if (i < ZZ*MM*DD) g_acc[i] = 0.f;
    if (i < ZZ*MM)    g_norm[i] = 0.f;
}

// =====================================================================
__global__ void softmax_slice(const float* __restrict__ scores, float* __restrict__ w)
{
    __shared__ float ss[256*33];
    const int z = blockIdx.y;
    const int n0 = blockIdx.x * 256;
    const int tid = threadIdx.x;

    const float* sb = scores + ((size_t)z*NN + n0) * MM;
    for (int i = tid; i < 256*MM; i += 256) {
        int n = i / MM, m = i % MM;
        ss[n*33 + m] = sb[i];
    }
    __syncthreads();

    float e[MM];
    float mx = -1e30f;
    #pragma unroll
    for (int m = 0; m < MM; m++) mx = fmaxf(mx, ss[tid*33 + m]);
    float sum = 0.f;
    #pragma unroll
    for (int m = 0; m < MM; m++) { e[m] = __expf(ss[tid*33 + m] - mx); sum += e[m]; }
    float inv = 1.f / sum;

    float* wb = w + (size_t)z*MM*NN + n0 + tid;
    #pragma unroll
    for (int m = 0; m < MM; m++) wb[(size_t)m*NN] = e[m] * inv;
}

// =====================================================================
__global__ void slice_token_kernel(const float* __restrict__ w)
{
    __shared__ float  ws[MM][64];
    __shared__ float4 xvs[64][32];
    const int z = blockIdx.y, c = blockIdx.x;
    const int b = z >> 3, h = z & 7;
    const int tid = threadIdx.x;

    const float* wb = w + (size_t)z*MM*NN + (size_t)c*64;
    for (int i = tid; i < MM*64; i += 256) {
        int m = i >> 6, n = i & 63;
        ws[m][n] = wb[(size_t)m*NN + n];
    }
    const float* vb = g_kv + ((size_t)(b*NN + c*64)) * (2*HDIM) + HDIM + h*DD;
    for (int i = tid; i < 64*32; i += 256) {
        int n = i >> 5, d4 = i & 31;
        xvs[n][d4] = *(const float4*)(vb + (size_t)n*(2*HDIM) + d4*4);
    }
    __syncthreads();

    if (tid < MM) {
        float s = 0.f;
        #pragma unroll 8
        for (int n = 0; n < 64; n++) s += ws[tid][n];
        atomicAdd(&g_norm[z*MM + tid], s);
    }

    const int d4 = tid & 31, mr = tid >> 5;
    float4 a[4];
    #pragma unroll
    for (int i = 0; i < 4; i++) a[i] = make_float4(0.f,0.f,0.f,0.f);

    #pragma unroll 4
    for (int n = 0; n < 64; n++) {
        float4 xv = xvs[n][d4];
        #pragma unroll
        for (int i = 0; i < 4; i++) {
            float wv = ws[mr*4 + i][n];
            a[i].x += wv*xv.x; a[i].y += wv*xv.y; a[i].z += wv*xv.z; a[i].w += wv*xv.w;
        }
    }
    float* ab = g_acc + (size_t)z*MM*DD + (mr*4)*DD + d4*4;
    #pragma unroll
    for (int i = 0; i < 4; i++) {
        atomicAdd(ab + i*DD + 0, a[i].x);
        atomicAdd(ab + i*DD + 1, a[i].y);
        atomicAdd(ab + i*DD + 2, a[i].z);
        atomicAdd(ab + i*DD + 3, a[i].w);
    }
}

// =====================================================================
__global__ void qkv_kernel(const float* __restrict__ proj)
{
    __shared__ float st[MM*DD];
    __shared__ float inv[MM];
    const int z = blockIdx.x, h = z & 7, tid = threadIdx.x;

    if (tid < MM) inv[tid] = 1.f / (g_norm[z*MM + tid] + 1e-5f);
    __syncthreads();
    for (int i = tid; i < MM*DD; i += 256) st[i] = g_acc[(size_t)z*MM*DD + i] * inv[i >> 7];
    __syncthreads();

    const float* P = proj + (size_t)h * DD * (3*DD);
    for (int i = tid; i < MM*3*DD; i += 256) {
        int m = i / (3*DD), e = i % (3*DD);
        float s = 0.f;
        #pragma unroll 8
        for (int d = 0; d < DD; d++) s += st[m*DD + d] * P[(size_t)d*(3*DD) + e];
        g_qkv[(size_t)z*MM*3*DD + i] = s;
    }
}

// =====================================================================
__global__ void attn_kernel(const float* __restrict__ wtq_bias, float* __restrict__ out)
{
    __shared__ float s_d[MM*MM];
    __shared__ float aw[MM*MM];
    const int z = blockIdx.x, tid = threadIdx.x;
    const float* Q  = g_qkv + (size_t)z*MM*3*DD;
    const float* Kt = Q + DD;
    const float* V  = Q + 2*DD;
    const float scale = 0.08838834764831845f;

    for (int i = tid; i < MM*MM; i += 256) {
        int q = i >> 5, k = i & 31;
        float s = 0.f;
        #pragma unroll 8
        for (int d = 0; d < DD; d++) s += Q[q*(3*DD) + d] * Kt[k*(3*DD) + d];
        s_d[i] = s * scale;
    }
    __syncthreads();

    if (tid < MM) {
        float mx = -1e30f;
        #pragma unroll
        for (int k = 0; k < MM; k++) mx = fmaxf(mx, s_d[tid*MM + k]);
        float sum = 0.f;
        #pragma unroll
        for (int k = 0; k < MM; k++) { float e = __expf(s_d[tid*MM + k] - mx); aw[tid*MM + k] = e; sum += e; }
        float iv = 1.f / sum;
        #pragma unroll
        for (int k = 0; k < MM; k++) {
            float v = aw[tid*MM + k] * iv;
            aw[tid*MM + k] = v;
            out[R5_ATTN + (size_t)z*MM*MM + tid*MM + k] = v;
        }
    }
    __syncthreads();

    for (int i = tid; i < MM*DD; i += 256) {
        int m = i >> 7, d = i & 127;
        float s = 0.f;
        #pragma unroll
        for (int k = 0; k < MM; k++) s += aw[m*MM + k] * V[k*(3*DD) + d];
        g_ot[(size_t)z*MM*DD + i] = s;
    }

    if (z == 0) {
        if (tid == 0) out[R3_TEMP] = 1.0f;
        if (tid < HH*MM) out[R4_BIAS + tid] = wtq_bias[tid];
    }
}

// =====================================================================
// Scatter — writes tf32-rounded values (feeds tc_gemm out-proj)
// =====================================================================
__global__ void scatter_kernel(const float* __restrict__ w)
{
    __shared__ float4 ot4[MM][32];
    __shared__ float  wsm[MM][33];
    const int z = blockIdx.y, t = blockIdx.x;
    const int b = z >> 3, h = z & 7, tid = threadIdx.x;

    for (int i = tid; i < MM*32; i += 256)
        ot4[i >> 5][i & 31] = ((const float4*)g_ot)[(size_t)z*MM*32 + i];

    const int n0 = t * 32;
    const float* wb = w + (size_t)z*MM*NN + n0;
    for (int i = tid; i < MM*32; i += 256) {
        int m = i >> 5, n = i & 31;
        wsm[m][n] = wb[(size_t)m*NN + n];
    }
    __syncthreads();

    const int d4 = tid & 31, nl = tid >> 5;
    #pragma unroll
    for (int p = 0; p < 4; p++) {
        int n = p*8 + nl;
        float4 a = make_float4(0.f,0.f,0.f,0.f);
        #pragma unroll
        for (int m = 0; m < MM; m++) {
            float wv = wsm[m][n];
            float4 o = ot4[m][d4];
            a.x += wv*o.x; a.y += wv*o.y; a.z += wv*o.z; a.w += wv*o.w;
        }
        float4 r;
        r.x = rtf32(a.x); r.y = rtf32(a.y); r.z = rtf32(a.z); r.w = rtf32(a.w);
        *(float4*)&g_out_pre[((size_t)(b*NN + n0 + n))*HDIM + h*DD + d4*4] = r;
    }
}

// =====================================================================
extern "C" void kernel_launch(void* const* d_in, const int* in_sizes, int n_in,
                              void* d_out, int out_size)
{
    const float* x         = (const float*)d_in[0];
    const float* wkv       = (const float*)d_in[1];
    const float* bkv       = (const float*)d_in[2];
    const float* wtq       = (const float*)d_in[3];
    const float* wtq_bias  = (const float*)d_in[4];
    const float* qkv_proj  = (const float*)d_in[5];
    const float* out_w     = (const float*)d_in[6];
    const float* out_b     = (const float*)d_in[7];
    float* out = (float*)d_out;

    float *kv, *scores, *out_pre, *xr, *wkvr, *owr;
    cudaGetSymbolAddress((void**)&kv, g_kv);
    cudaGetSymbolAddress((void**)&scores, g_scores);
    cudaGetSymbolAddress((void**)&out_pre, g_out_pre);
    cudaGetSymbolAddress((void**)&xr, g_xr);
    cudaGetSymbolAddress((void**)&wkvr, g_wkvr);
    cudaGetSymbolAddress((void**)&owr, g_owr);

    cudaFuncSetAttribute(tc_gemm, cudaFuncAttributeMaxDynamicSharedMemorySize, TC_DSMEM);

    float* sw = out + R2_SW;

    // 0) zero split-K accumulators
    zero_kernel<<<(ZZ*MM*DD + 255)/256, 256>>>();

    // 0b) round GEMM inputs to nearest-tf32 (unbiased)
    round_tf32_kernel<<<(BN_TOK*HDIM/4 + 255)/256, 256>>>(x, xr, BN_TOK*HDIM/4);
    round_tf32_kernel<<<(2*HDIM*HDIM/4 + 255)/256, 256>>>(wkv, wkvr, 2*HDIM*HDIM/4);
    round_tf32_kernel<<<(HDIM*HDIM/4 + 255)/256, 256>>>(out_w, owr, HDIM*HDIM/4);

    // 1) kv = x @ Wkv^T + b  — tensor-core tf32
    tc_gemm<<<dim3(2*HDIM/TC_BN, BN_TOK/TC_BM), 256, TC_DSMEM>>>(
        xr, wkvr, bkv, kv, HDIM, HDIM, 2*HDIM, HDIM);

    // 2) slice_scores (batched small SGEMM, fp32)
    sgemm_nt<128,32,16,8,4><<<dim3(1, NN/128, ZZ), 128>>>(
        kv, wtq, scores, nullptr, DD, 2*HDIM, DD, MM,
        HH,
        (long)NN*2*HDIM, (long)DD,
        0,               (long)MM*DD,
        (long)HH*NN*MM,  (long)NN*MM);

    // 3) softmax over m + transpose -> slice_weights (in d_out)
    softmax_slice<<<dim3(NN/256, ZZ), 256>>>(scores, sw);

    // 4) slice_token split-K + norm
    slice_token_kernel<<<dim3(NN/64, ZZ), 256>>>(sw);

    // 5) normalize + qkv projection
    qkv_kernel<<<ZZ, 256>>>(qkv_proj);

    // 6) tiny attention + aux outputs
    attn_kernel<<<ZZ, 256>>>(wtq_bias, out);

    // 7) scatter (tf32-rounded out_pre)
    scatter_kernel<<<dim3(NN/32, ZZ), 256>>>(sw);

    // 8) out = out_pre @ Wout^T + b — tensor-core tf32
    tc_gemm<<<dim3(HDIM/TC_BN, BN_TOK/TC_BM), 256, TC_DSMEM>>>(
        out_pre, owr, out_b, out, HDIM, HDIM, HDIM, HDIM);
}